// round 6
// baseline (speedup 1.0000x reference)
#include <cuda_runtime.h>

#define NN 100000
#define NE 1600000
#define DIM 128

#define SCAN_B 512
#define SCAN_NBLK ((NN + SCAN_B - 1) / SCAN_B)   // 196

// ---------------- scratch (static device memory; no allocs) ----------------
__device__ __align__(16) float g_deg[NN];
__device__ __align__(16) float g_dinv[NN];
__device__ __align__(16) int   g_cnt[NN];
__device__ __align__(16) int   g_off[NN];
__device__ __align__(16) int   g_cursor[NN];
__device__ __align__(16) int   g_srow[NE];
__device__ __align__(16) float g_snorm[NE];
__device__ __align__(16) float g_h[(size_t)NN * DIM];   // pre-aggregation features (A @ W)
__device__ __align__(16) float g_z[(size_t)NN * DIM];   // layer-1 output
__device__ __align__(16) int   g_bsum[SCAN_NBLK];
__device__ int g_is64;                                   // edge_index dtype flag

// ---------------- dtype detection ----------------
// int64 little-endian values < 2^31: every odd 32-bit word is 0.
// int32 data: odd words are random node indices -> virtually never all zero.
__global__ void k_detect(const int* __restrict__ ei32) {
    if (blockIdx.x == 0 && threadIdx.x == 0) {
        int is64 = 1;
        for (int i = 0; i < 64; i++)
            if (ei32[2 * i + 1] != 0) { is64 = 0; break; }
        g_is64 = is64;
    }
}

__device__ __forceinline__ int edge_at(const void* ei, int is64, size_t pos) {
    return is64 ? (int)((const long long*)ei)[pos] : ((const int*)ei)[pos];
}

// ---------------- degree / histogram ----------------
__global__ void k_init() {
    int i = blockIdx.x * blockDim.x + threadIdx.x;
    if (i < NN) { g_deg[i] = 1.0f; g_cnt[i] = 0; }   // self-loop weight 1
}

__global__ void k_hist(const void* __restrict__ ei, const float* __restrict__ ew) {
    int e = blockIdx.x * blockDim.x + threadIdx.x;
    if (e < NE) {
        int is64 = g_is64;
        int c = edge_at(ei, is64, (size_t)NE + e);   // col (destination)
        if ((unsigned)c < NN) {
            atomicAdd(&g_deg[c], ew[e]);
            atomicAdd(&g_cnt[c], 1);
        }
    }
}

__global__ void k_dinv() {
    int i = blockIdx.x * blockDim.x + threadIdx.x;
    if (i < NN) {
        float d = g_deg[i];
        g_dinv[i] = (d > 0.0f) ? rsqrtf(d) : 0.0f;
    }
}

// ---------------- exclusive scan of g_cnt -> g_off (3-kernel) ----------------
__global__ void k_scan1() {
    __shared__ int s[SCAN_B];
    int i = blockIdx.x * SCAN_B + threadIdx.x;
    s[threadIdx.x] = (i < NN) ? g_cnt[i] : 0;
    __syncthreads();
    for (int st = SCAN_B / 2; st > 0; st >>= 1) {
        if ((int)threadIdx.x < st) s[threadIdx.x] += s[threadIdx.x + st];
        __syncthreads();
    }
    if (threadIdx.x == 0) g_bsum[blockIdx.x] = s[0];
}

__global__ void k_scan2() {
    int acc = 0;
    for (int i = 0; i < SCAN_NBLK; i++) { int v = g_bsum[i]; g_bsum[i] = acc; acc += v; }
}

__global__ void k_scan3() {
    __shared__ int s[SCAN_B];
    int i = blockIdx.x * SCAN_B + threadIdx.x;
    int v = (i < NN) ? g_cnt[i] : 0;
    s[threadIdx.x] = v;
    __syncthreads();
    // Hillis-Steele inclusive scan
    for (int st = 1; st < SCAN_B; st <<= 1) {
        int t = 0;
        if ((int)threadIdx.x >= st) t = s[threadIdx.x - st];
        __syncthreads();
        if ((int)threadIdx.x >= st) s[threadIdx.x] += t;
        __syncthreads();
    }
    if (i < NN) {
        int excl = g_bsum[blockIdx.x] + s[threadIdx.x] - v;
        g_off[i]    = excl;
        g_cursor[i] = excl;
    }
}

// ---------------- bucket edges by destination (CSC build) ----------------
__global__ void k_scatter(const void* __restrict__ ei, const float* __restrict__ ew) {
    int e = blockIdx.x * blockDim.x + threadIdx.x;
    if (e < NE) {
        int is64 = g_is64;
        int r = edge_at(ei, is64, e);
        int c = edge_at(ei, is64, (size_t)NE + e);
        if ((unsigned)r < NN && (unsigned)c < NN) {
            int pos = atomicAdd(&g_cursor[c], 1);
            g_srow[pos]  = r;
            g_snorm[pos] = g_dinv[r] * ew[e] * g_dinv[c];
        }
    }
}

// ---------------- GEMM: g_h[NN,128] = A[NN,128] @ W[128,128] ----------------
// BM=128, BN=128(=DIM), BK=16, 256 threads, 8x8 register tile.
// FROM_GZ=false: A = x (kernel parameter). FROM_GZ=true: A = g_z (symbol).
#define GEMM_BM 128
#define GEMM_BK 16

template<bool FROM_GZ>
__global__ __launch_bounds__(256) void k_gemm(const float* __restrict__ Ain,
                                              const float* __restrict__ W) {
    const float* A = FROM_GZ ? (const float*)g_z : Ain;

    __shared__ float As[GEMM_BK][GEMM_BM];
    __shared__ float Bs[GEMM_BK][DIM];
    int tid = threadIdx.x;
    int tr = tid / 16;      // 0..15 -> row group
    int tc = tid % 16;      // 0..15 -> col group
    int rowBase = blockIdx.x * GEMM_BM;

    float acc[8][8];
    #pragma unroll
    for (int i = 0; i < 8; i++)
        #pragma unroll
        for (int j = 0; j < 8; j++) acc[i][j] = 0.0f;

    for (int k0 = 0; k0 < DIM; k0 += GEMM_BK) {
        // Load A tile (128 rows x 16 k): 512 float4, 2 per thread; store transposed.
        #pragma unroll
        for (int l = 0; l < 2; l++) {
            int idx = tid + l * 256;
            int r  = idx >> 2;
            int cg = (idx & 3) * 4;
            float4 a = make_float4(0.f, 0.f, 0.f, 0.f);
            int grow = rowBase + r;
            if (grow < NN) a = *(const float4*)&A[(size_t)grow * DIM + k0 + cg];
            As[cg + 0][r] = a.x; As[cg + 1][r] = a.y;
            As[cg + 2][r] = a.z; As[cg + 3][r] = a.w;
        }
        // Load B tile (16 k x 128 n)
        #pragma unroll
        for (int l = 0; l < 2; l++) {
            int idx = tid + l * 256;
            int r  = idx >> 5;
            int cg = (idx & 31) * 4;
            *(float4*)&Bs[r][cg] = *(const float4*)&W[(size_t)(k0 + r) * DIM + cg];
        }
        __syncthreads();

        #pragma unroll
        for (int k = 0; k < GEMM_BK; k++) {
            float a[8], b[8];
            #pragma unroll
            for (int i = 0; i < 8; i += 4) *(float4*)&a[i] = *(float4*)&As[k][tr * 8 + i];
            #pragma unroll
            for (int j = 0; j < 8; j += 4) *(float4*)&b[j] = *(float4*)&Bs[k][tc * 8 + j];
            #pragma unroll
            for (int i = 0; i < 8; i++)
                #pragma unroll
                for (int j = 0; j < 8; j++)
                    acc[i][j] += a[i] * b[j];
        }
        __syncthreads();
    }

    #pragma unroll
    for (int i = 0; i < 8; i++) {
        int grow = rowBase + tr * 8 + i;
        if (grow < NN) {
            #pragma unroll
            for (int j = 0; j < 8; j += 4) {
                *(float4*)&g_h[(size_t)grow * DIM + tc * 8 + j] =
                    make_float4(acc[i][j], acc[i][j + 1], acc[i][j + 2], acc[i][j + 3]);
            }
        }
    }
}

// ---------------- aggregation: one warp per node ----------------
// dst[i] = relu( bias + dinv[i]^2 * g_h[i] + sum_e norm[e] * g_h[srow[e]] )
// TO_OUT=false: dst = g_z (symbol). TO_OUT=true: dst = out parameter.
template<bool TO_OUT>
__global__ __launch_bounds__(256) void k_agg(const float* __restrict__ bias,
                                             float* __restrict__ outp) {
    int warp = (blockIdx.x * blockDim.x + threadIdx.x) >> 5;
    int lane = threadIdx.x & 31;
    if (warp >= NN) return;
    int node = warp;

    const float4* h4 = (const float4*)g_h;
    float di = g_dinv[node];
    float sn = di * di;              // self-loop norm (weight 1)

    float4 hv = h4[(size_t)node * 32 + lane];
    float4 acc = make_float4(hv.x * sn, hv.y * sn, hv.z * sn, hv.w * sn);

    int start = g_off[node];
    int cnt   = g_cnt[node];

    int e = 0;
    for (; e + 2 <= cnt; e += 2) {
        int   r0 = g_srow[start + e];
        int   r1 = g_srow[start + e + 1];
        float n0 = g_snorm[start + e];
        float n1 = g_snorm[start + e + 1];
        float4 v0 = h4[(size_t)r0 * 32 + lane];
        float4 v1 = h4[(size_t)r1 * 32 + lane];
        acc.x += n0 * v0.x; acc.y += n0 * v0.y; acc.z += n0 * v0.z; acc.w += n0 * v0.w;
        acc.x += n1 * v1.x; acc.y += n1 * v1.y; acc.z += n1 * v1.z; acc.w += n1 * v1.w;
    }
    if (e < cnt) {
        int   r0 = g_srow[start + e];
        float n0 = g_snorm[start + e];
        float4 v0 = h4[(size_t)r0 * 32 + lane];
        acc.x += n0 * v0.x; acc.y += n0 * v0.y; acc.z += n0 * v0.z; acc.w += n0 * v0.w;
    }

    float4 bb = ((const float4*)bias)[lane];
    acc.x = fmaxf(acc.x + bb.x, 0.0f);
    acc.y = fmaxf(acc.y + bb.y, 0.0f);
    acc.z = fmaxf(acc.z + bb.z, 0.0f);
    acc.w = fmaxf(acc.w + bb.w, 0.0f);

    float4* dst = TO_OUT ? (float4*)outp : (float4*)g_z;
    dst[(size_t)node * 32 + lane] = acc;
}

// ---------------- launch: kernel launches ONLY ----------------
extern "C" void kernel_launch(void* const* d_in, const int* in_sizes, int n_in,
                              void* d_out, int out_size) {
    const float* x  = (const float*)d_in[0];
    const void*  ei = d_in[1];                    // int32 or int64 -> detected on device
    const float* ew = (const float*)d_in[2];
    const float* W1 = (const float*)d_in[3];
    const float* b1 = (const float*)d_in[4];
    const float* W2 = (const float*)d_in[5];
    const float* b2 = (const float*)d_in[6];
    float* out = (float*)d_out;

    // --- dtype detect + gcn_norm + CSC build ---
    k_detect<<<1, 32>>>((const int*)ei);
    k_init<<<(NN + 255) / 256, 256>>>();
    k_hist<<<(NE + 255) / 256, 256>>>(ei, ew);
    k_dinv<<<(NN + 255) / 256, 256>>>();
    k_scan1<<<SCAN_NBLK, SCAN_B>>>();
    k_scan2<<<1, 1>>>();
    k_scan3<<<SCAN_NBLK, SCAN_B>>>();
    k_scatter<<<(NE + 255) / 256, 256>>>(ei, ew);

    const int gemm_grid = (NN + GEMM_BM - 1) / GEMM_BM;   // 782
    const int agg_grid  = (NN + 7) / 8;                    // 12500 (8 warps/block)

    // --- layer 1 ---
    k_gemm<false><<<gemm_grid, 256>>>(x, W1);
    k_agg<false><<<agg_grid, 256>>>(b1, nullptr);

    // --- layer 2 ---
    k_gemm<true><<<gemm_grid, 256>>>(nullptr, W2);
    k_agg<true><<<agg_grid, 256>>>(b2, out);
}

// round 7
// speedup vs baseline: 1.1159x; 1.1159x over previous
#include <cuda_runtime.h>
#include <cuda_fp16.h>

#define NN 100000
#define NE 1600000
#define DIM 128

#define SCAN_B 512
#define SCAN_NBLK ((NN + SCAN_B - 1) / SCAN_B)   // 196

typedef unsigned long long u64;

// ---------------- scratch (static device memory; no allocs) ----------------
__device__ __align__(16) float  g_deg[NN];
__device__ __align__(16) float  g_dinv[NN];
__device__ __align__(16) int    g_cnt[NN];
__device__ __align__(16) int    g_off[NN];
__device__ __align__(16) int    g_cursor[NN];
__device__ __align__(16) int2   g_edge[NE];               // (src row, norm as int bits)
__device__ __align__(16) __half g_h[(size_t)NN * DIM];    // pre-agg features (A @ W), fp16
__device__ __align__(16) float  g_z[(size_t)NN * DIM];    // layer-1 output, fp32
__device__ __align__(16) int    g_bsum[SCAN_NBLK];
__device__ int g_is64;                                    // edge_index dtype flag

// ---------------- f32x2 packed-math helpers (SASS: FFMA2 — 2x fp32 tput) ----
__device__ __forceinline__ void ffma2(u64 &c, u64 a, u64 b) {
    asm("fma.rn.f32x2 %0, %1, %2, %0;" : "+l"(c) : "l"(a), "l"(b));
}
__device__ __forceinline__ u64 pack2(float lo, float hi) {
    u64 r; asm("mov.b64 %0, {%1, %2};" : "=l"(r) : "f"(lo), "f"(hi)); return r;
}
__device__ __forceinline__ float2 unpack2(u64 v) {
    float2 f; asm("mov.b64 {%0, %1}, %2;" : "=f"(f.x), "=f"(f.y) : "l"(v)); return f;
}

// ---------------- init (+ edge dtype detect) ----------------
// int64 little-endian values < 2^31: every odd 32-bit word is 0.
// int32 data: odd words are random node indices -> virtually never all zero.
__global__ void k_init(const int* __restrict__ ei32) {
    int i = blockIdx.x * blockDim.x + threadIdx.x;
    if (i < NN) { g_deg[i] = 1.0f; g_cnt[i] = 0; }   // self-loop weight 1
    if (blockIdx.x == 0 && threadIdx.x == 0) {
        int is64 = 1;
        for (int j = 0; j < 64; j++)
            if (ei32[2 * j + 1] != 0) { is64 = 0; break; }
        g_is64 = is64;
    }
}

__device__ __forceinline__ int edge_at(const void* ei, int is64, size_t pos) {
    return is64 ? (int)((const long long*)ei)[pos] : ((const int*)ei)[pos];
}

// ---------------- degree / histogram ----------------
__global__ void k_hist(const void* __restrict__ ei, const float* __restrict__ ew) {
    int e = blockIdx.x * blockDim.x + threadIdx.x;
    if (e < NE) {
        int is64 = g_is64;
        int c = edge_at(ei, is64, (size_t)NE + e);   // col (destination)
        if ((unsigned)c < NN) {
            atomicAdd(&g_deg[c], ew[e]);
            atomicAdd(&g_cnt[c], 1);
        }
    }
}

// ---------------- scan phase 1 (+ dinv fused) ----------------
__global__ void k_scan1() {
    __shared__ int s[SCAN_B];
    int i = blockIdx.x * SCAN_B + threadIdx.x;
    s[threadIdx.x] = (i < NN) ? g_cnt[i] : 0;
    if (i < NN) {
        float d = g_deg[i];
        g_dinv[i] = (d > 0.0f) ? rsqrtf(d) : 0.0f;
    }
    __syncthreads();
    for (int st = SCAN_B / 2; st > 0; st >>= 1) {
        if ((int)threadIdx.x < st) s[threadIdx.x] += s[threadIdx.x + st];
        __syncthreads();
    }
    if (threadIdx.x == 0) g_bsum[blockIdx.x] = s[0];
}

__global__ void k_scan2() {
    int acc = 0;
    for (int i = 0; i < SCAN_NBLK; i++) { int v = g_bsum[i]; g_bsum[i] = acc; acc += v; }
}

__global__ void k_scan3() {
    __shared__ int s[SCAN_B];
    int i = blockIdx.x * SCAN_B + threadIdx.x;
    int v = (i < NN) ? g_cnt[i] : 0;
    s[threadIdx.x] = v;
    __syncthreads();
    for (int st = 1; st < SCAN_B; st <<= 1) {
        int t = 0;
        if ((int)threadIdx.x >= st) t = s[threadIdx.x - st];
        __syncthreads();
        if ((int)threadIdx.x >= st) s[threadIdx.x] += t;
        __syncthreads();
    }
    if (i < NN) {
        int excl = g_bsum[blockIdx.x] + s[threadIdx.x] - v;
        g_off[i]    = excl;
        g_cursor[i] = excl;
    }
}

// ---------------- bucket edges by destination (CSC build) ----------------
__global__ void k_scatter(const void* __restrict__ ei, const float* __restrict__ ew) {
    int e = blockIdx.x * blockDim.x + threadIdx.x;
    if (e < NE) {
        int is64 = g_is64;
        int r = edge_at(ei, is64, e);
        int c = edge_at(ei, is64, (size_t)NE + e);
        if ((unsigned)r < NN && (unsigned)c < NN) {
            int pos = atomicAdd(&g_cursor[c], 1);
            float nrm = g_dinv[r] * ew[e] * g_dinv[c];
            g_edge[pos] = make_int2(r, __float_as_int(nrm));
        }
    }
}

// ---------------- GEMM: g_h(fp16)[NN,128] = A[NN,128] @ W[128,128] ----------
// BM=128, BN=128(=DIM), BK=16, 256 threads, 8x8 register tile via f32x2 FFMA2.
// FROM_GZ=false: A = x (kernel parameter). FROM_GZ=true: A = g_z (symbol).
#define GEMM_BM 128
#define GEMM_BK 16

template<bool FROM_GZ>
__global__ __launch_bounds__(256) void k_gemm(const float* __restrict__ Ain,
                                              const float* __restrict__ W) {
    const float* A = FROM_GZ ? (const float*)g_z : Ain;

    __shared__ float As[GEMM_BK][GEMM_BM];
    __shared__ float Bs[GEMM_BK][DIM];
    int tid = threadIdx.x;
    int tr = tid / 16;      // 0..15 -> row group
    int tc = tid % 16;      // 0..15 -> col group
    int rowBase = blockIdx.x * GEMM_BM;

    // acc2[i][j2]: row i (0..7), column pair j2 (0..3) -> cols tc*8 + 2*j2 + {0,1}
    u64 acc2[8][4];
    #pragma unroll
    for (int i = 0; i < 8; i++)
        #pragma unroll
        for (int j = 0; j < 4; j++) acc2[i][j] = 0ull;

    for (int k0 = 0; k0 < DIM; k0 += GEMM_BK) {
        // Load A tile (128 rows x 16 k): 512 float4, 2 per thread; store transposed.
        #pragma unroll
        for (int l = 0; l < 2; l++) {
            int idx = tid + l * 256;
            int r  = idx >> 2;
            int cg = (idx & 3) * 4;
            float4 a = make_float4(0.f, 0.f, 0.f, 0.f);
            int grow = rowBase + r;
            if (grow < NN) a = *(const float4*)&A[(size_t)grow * DIM + k0 + cg];
            As[cg + 0][r] = a.x; As[cg + 1][r] = a.y;
            As[cg + 2][r] = a.z; As[cg + 3][r] = a.w;
        }
        // Load B tile (16 k x 128 n)
        #pragma unroll
        for (int l = 0; l < 2; l++) {
            int idx = tid + l * 256;
            int r  = idx >> 5;
            int cg = (idx & 31) * 4;
            *(float4*)&Bs[r][cg] = *(const float4*)&W[(size_t)(k0 + r) * DIM + cg];
        }
        __syncthreads();

        #pragma unroll
        for (int k = 0; k < GEMM_BK; k++) {
            float4 aA = *(float4*)&As[k][tr * 8];
            float4 aB = *(float4*)&As[k][tr * 8 + 4];
            float4 bA = *(float4*)&Bs[k][tc * 8];
            float4 bB = *(float4*)&Bs[k][tc * 8 + 4];
            u64 b2[4];
            b2[0] = pack2(bA.x, bA.y); b2[1] = pack2(bA.z, bA.w);
            b2[2] = pack2(bB.x, bB.y); b2[3] = pack2(bB.z, bB.w);
            float av[8] = {aA.x, aA.y, aA.z, aA.w, aB.x, aB.y, aB.z, aB.w};
            #pragma unroll
            for (int i = 0; i < 8; i++) {
                u64 ad = pack2(av[i], av[i]);
                #pragma unroll
                for (int j = 0; j < 4; j++) ffma2(acc2[i][j], ad, b2[j]);
            }
        }
        __syncthreads();
    }

    // Epilogue: convert to fp16, one 16B store per row (8 cols).
    #pragma unroll
    for (int i = 0; i < 8; i++) {
        int grow = rowBase + tr * 8 + i;
        if (grow < NN) {
            uint4 v;
            __half2 p0 = __float22half2_rn(unpack2(acc2[i][0]));
            __half2 p1 = __float22half2_rn(unpack2(acc2[i][1]));
            __half2 p2 = __float22half2_rn(unpack2(acc2[i][2]));
            __half2 p3 = __float22half2_rn(unpack2(acc2[i][3]));
            v.x = *(unsigned*)&p0; v.y = *(unsigned*)&p1;
            v.z = *(unsigned*)&p2; v.w = *(unsigned*)&p3;
            *(uint4*)&g_h[(size_t)grow * DIM + tc * 8] = v;
        }
    }
}

// ---------------- aggregation: one warp per node ----------------
// dst[i] = relu( bias + dinv[i]^2 * g_h[i] + sum_e norm[e] * g_h[srow[e]] )
// TO_OUT=false: dst = g_z (symbol). TO_OUT=true: dst = out parameter.
__device__ __forceinline__ void gather_fma(float4 &acc, float n, uint2 raw) {
    float2 f01 = __half22float2(*(__half2*)&raw.x);
    float2 f23 = __half22float2(*(__half2*)&raw.y);
    acc.x += n * f01.x; acc.y += n * f01.y;
    acc.z += n * f23.x; acc.w += n * f23.y;
}

template<bool TO_OUT>
__global__ __launch_bounds__(256) void k_agg(const float* __restrict__ bias,
                                             float* __restrict__ outp) {
    int warp = (blockIdx.x * blockDim.x + threadIdx.x) >> 5;
    int lane = threadIdx.x & 31;
    if (warp >= NN) return;
    int node = warp;

    float di = g_dinv[node];
    float sn = di * di;              // self-loop norm (weight 1)

    // each lane covers 4 dims: one uint2 (4 halfs) per row
    const uint2* hrow = (const uint2*)(g_h + (size_t)node * DIM);
    float4 acc = make_float4(0.f, 0.f, 0.f, 0.f);
    gather_fma(acc, sn, hrow[lane]);

    int start = g_off[node];
    int cnt   = g_cnt[node];

    int e = 0;
    for (; e + 2 <= cnt; e += 2) {
        int2 e0 = g_edge[start + e];
        int2 e1 = g_edge[start + e + 1];
        uint2 v0 = ((const uint2*)(g_h + (size_t)e0.x * DIM))[lane];
        uint2 v1 = ((const uint2*)(g_h + (size_t)e1.x * DIM))[lane];
        gather_fma(acc, __int_as_float(e0.y), v0);
        gather_fma(acc, __int_as_float(e1.y), v1);
    }
    if (e < cnt) {
        int2 e0 = g_edge[start + e];
        uint2 v0 = ((const uint2*)(g_h + (size_t)e0.x * DIM))[lane];
        gather_fma(acc, __int_as_float(e0.y), v0);
    }

    float4 bb = ((const float4*)bias)[lane];
    acc.x = fmaxf(acc.x + bb.x, 0.0f);
    acc.y = fmaxf(acc.y + bb.y, 0.0f);
    acc.z = fmaxf(acc.z + bb.z, 0.0f);
    acc.w = fmaxf(acc.w + bb.w, 0.0f);

    float4* dst = TO_OUT ? (float4*)outp : (float4*)g_z;
    dst[(size_t)node * 32 + lane] = acc;
}

// ---------------- launch: kernel launches ONLY ----------------
extern "C" void kernel_launch(void* const* d_in, const int* in_sizes, int n_in,
                              void* d_out, int out_size) {
    const float* x  = (const float*)d_in[0];
    const void*  ei = d_in[1];                    // int32 or int64 -> detected on device
    const float* ew = (const float*)d_in[2];
    const float* W1 = (const float*)d_in[3];
    const float* b1 = (const float*)d_in[4];
    const float* W2 = (const float*)d_in[5];
    const float* b2 = (const float*)d_in[6];
    float* out = (float*)d_out;

    const int gemm_grid = (NN + GEMM_BM - 1) / GEMM_BM;   // 782
    const int agg_grid  = (NN + 7) / 8;                    // 12500 (8 warps/block)

    // --- build + layer pipeline (gemm1 hoisted: independent of CSC build) ---
    k_init<<<(NN + 255) / 256, 256>>>((const int*)ei);
    k_hist<<<(NE + 255) / 256, 256>>>(ei, ew);
    k_scan1<<<SCAN_NBLK, SCAN_B>>>();
    k_scan2<<<1, 1>>>();
    k_scan3<<<SCAN_NBLK, SCAN_B>>>();
    k_gemm<false><<<gemm_grid, 256>>>(x, W1);     // x @ W1 -> g_h (fp16)
    k_scatter<<<(NE + 255) / 256, 256>>>(ei, ew);

    // --- layer 1 aggregate ---
    k_agg<false><<<agg_grid, 256>>>(b1, nullptr); // -> g_z (fp32)

    // --- layer 2 ---
    k_gemm<true><<<gemm_grid, 256>>>(nullptr, W2);
    k_agg<true><<<agg_grid, 256>>>(b2, out);
}

// round 9
// speedup vs baseline: 1.4760x; 1.3227x over previous
#include <cuda_runtime.h>
#include <cuda_fp16.h>

#define NN 100000
#define NE 1600000
#define DIM 128

#define SCAN_B 512
#define SCAN_NBLK ((NN + SCAN_B - 1) / SCAN_B)   // 196

typedef unsigned long long u64;

// ---------------- scratch (static device memory; no allocs) ----------------
__device__ __align__(16) float  g_deg[NN];     // 1 + sum(ew-1) during hist
__device__ __align__(16) float  g_dinv[NN];
__device__ __align__(16) int    g_cnt[NN];
__device__ __align__(16) int    g_off[NN];
__device__ __align__(16) int    g_cursor[NN];
__device__ __align__(16) int2   g_edge[NE];               // (src row, norm as int bits)
__device__ __align__(16) __half g_h[(size_t)NN * DIM];    // pre-agg features (A @ W), fp16
__device__ __align__(16) float  g_z[(size_t)NN * DIM];    // layer-1 output, fp32
__device__ __align__(16) int    g_bsum[SCAN_NBLK];
__device__ int g_is64;                                    // edge_index dtype flag

// ---------------- init (+ edge dtype detect) ----------------
__global__ void k_init(const int* __restrict__ ei32) {
    int i = blockIdx.x * blockDim.x + threadIdx.x;
    if (i < NN) { g_deg[i] = 1.0f; g_cnt[i] = 0; }   // self-loop weight 1
    if (blockIdx.x == 0 && threadIdx.x == 0) {
        int is64 = 1;
        for (int j = 0; j < 64; j++)
            if (ei32[2 * j + 1] != 0) { is64 = 0; break; }
        g_is64 = is64;
    }
}

__device__ __forceinline__ int edge_at(const void* ei, int is64, size_t pos) {
    return is64 ? (int)((const long long*)ei)[pos] : ((const int*)ei)[pos];
}

// ---------------- degree / histogram ----------------
// deg = 1 + sum(ew). We count edges with an int atomic; the float atomic fires
// only for ew != 1 (never, for unit weights). scan1 reconstructs deg = g_deg + cnt.
__global__ void k_hist(const void* __restrict__ ei, const float* __restrict__ ew) {
    int e = blockIdx.x * blockDim.x + threadIdx.x;
    if (e < NE) {
        int is64 = g_is64;
        int c = edge_at(ei, is64, (size_t)NE + e);   // col (destination)
        if ((unsigned)c < NN) {
            atomicAdd(&g_cnt[c], 1);
            float w = ew[e];
            if (w != 1.0f) atomicAdd(&g_deg[c], w - 1.0f);
        }
    }
}

// ---------------- scan phase 1 (+ dinv fused) ----------------
__global__ void k_scan1() {
    __shared__ int s[SCAN_B];
    int i = blockIdx.x * SCAN_B + threadIdx.x;
    int cnt = (i < NN) ? g_cnt[i] : 0;
    s[threadIdx.x] = cnt;
    if (i < NN) {
        float d = g_deg[i] + (float)cnt;
        g_dinv[i] = (d > 0.0f) ? rsqrtf(d) : 0.0f;
    }
    __syncthreads();
    for (int st = SCAN_B / 2; st > 0; st >>= 1) {
        if ((int)threadIdx.x < st) s[threadIdx.x] += s[threadIdx.x + st];
        __syncthreads();
    }
    if (threadIdx.x == 0) g_bsum[blockIdx.x] = s[0];
}

// parallel 196-element exclusive scan (single block)
__global__ void k_scan2() {
    __shared__ int s[256];
    int t = threadIdx.x;
    int v = (t < SCAN_NBLK) ? g_bsum[t] : 0;
    s[t] = v;
    __syncthreads();
    for (int st = 1; st < 256; st <<= 1) {
        int u = 0;
        if (t >= st) u = s[t - st];
        __syncthreads();
        s[t] += u;
        __syncthreads();
    }
    if (t < SCAN_NBLK) g_bsum[t] = s[t] - v;   // exclusive
}

__global__ void k_scan3() {
    __shared__ int s[SCAN_B];
    int i = blockIdx.x * SCAN_B + threadIdx.x;
    int v = (i < NN) ? g_cnt[i] : 0;
    s[threadIdx.x] = v;
    __syncthreads();
    for (int st = 1; st < SCAN_B; st <<= 1) {
        int t = 0;
        if ((int)threadIdx.x >= st) t = s[threadIdx.x - st];
        __syncthreads();
        if ((int)threadIdx.x >= st) s[threadIdx.x] += t;
        __syncthreads();
    }
    if (i < NN) {
        int excl = g_bsum[blockIdx.x] + s[threadIdx.x] - v;
        g_off[i]    = excl;
        g_cursor[i] = excl;
    }
}

// ---------------- bucket edges by destination (CSC build) ----------------
__global__ void k_scatter(const void* __restrict__ ei, const float* __restrict__ ew) {
    int e = blockIdx.x * blockDim.x + threadIdx.x;
    if (e < NE) {
        int is64 = g_is64;
        int r = edge_at(ei, is64, e);
        int c = edge_at(ei, is64, (size_t)NE + e);
        if ((unsigned)r < NN && (unsigned)c < NN) {
            int pos = atomicAdd(&g_cursor[c], 1);
            float nrm = g_dinv[r] * ew[e] * g_dinv[c];
            g_edge[pos] = make_int2(r, __float_as_int(nrm));
        }
    }
}

// ---------------- tensor-core GEMM: g_h(fp16) = A[NN,128] @ W[128,128] -----
// mma.sync m16n8k16 f16 inputs / f32 accum. 256 threads = 8 warps, each warp
// owns m16 x n128. W held fully in smem (fp16, rows padded to 136 halves so
// ldmatrix.trans is bank-conflict-free). A streamed in k=32 fp16 chunks
// (rows padded to 40 halves -> conflict-free ldmatrix).
#define GEMM_BM 128

__device__ __forceinline__ void mma16816(float* c, unsigned a0, unsigned a1,
                                         unsigned a2, unsigned a3,
                                         unsigned b0, unsigned b1) {
    asm volatile(
        "mma.sync.aligned.m16n8k16.row.col.f32.f16.f16.f32 "
        "{%0,%1,%2,%3}, {%4,%5,%6,%7}, {%8,%9}, {%0,%1,%2,%3};"
        : "+f"(c[0]), "+f"(c[1]), "+f"(c[2]), "+f"(c[3])
        : "r"(a0), "r"(a1), "r"(a2), "r"(a3), "r"(b0), "r"(b1));
}

template<bool FROM_GZ>
__global__ __launch_bounds__(256) void k_gemm(const float* __restrict__ Ain,
                                              const float* __restrict__ W) {
    const float* A = FROM_GZ ? (const float*)g_z : Ain;

    __shared__ __half Ws[128][136];   // full W, k-major rows, padded
    __shared__ __half As[128][40];    // one k=32 chunk of A, padded

    int tid  = threadIdx.x;
    int wid  = tid >> 5;
    int lane = tid & 31;
    int rowBase = blockIdx.x * GEMM_BM;
    int m_base  = wid * 16;

    // Load + convert W (4096 float4 = 16384 floats)
    for (int i = tid; i < 4096; i += 256) {
        int r = i >> 5;              // 32 float4 per 128-col row
        int c = (i & 31) * 4;
        float4 w4 = *(const float4*)&W[r * DIM + c];
        *(__half2*)&Ws[r][c]     = __floats2half2_rn(w4.x, w4.y);
        *(__half2*)&Ws[r][c + 2] = __floats2half2_rn(w4.z, w4.w);
    }

    float acc[16][4];                // 16 n8-tiles x 4 regs
    #pragma unroll
    for (int i = 0; i < 16; i++)
        #pragma unroll
        for (int j = 0; j < 4; j++) acc[i][j] = 0.0f;

    for (int kc = 0; kc < 4; kc++) {
        int k0g = kc * 32;
        __syncthreads();             // As reuse fence (covers Ws on iter 0)
        // Load A chunk: 128 rows x 32 cols (1024 float4)
        for (int i = tid; i < 1024; i += 256) {
            int r = i >> 3;          // 8 float4 per row
            int c = (i & 7) * 4;
            int grow = rowBase + r;
            float4 a4 = (grow < NN)
                ? *(const float4*)&A[(size_t)grow * DIM + k0g + c]
                : make_float4(0.f, 0.f, 0.f, 0.f);
            *(__half2*)&As[r][c]     = __floats2half2_rn(a4.x, a4.y);
            *(__half2*)&As[r][c + 2] = __floats2half2_rn(a4.z, a4.w);
        }
        __syncthreads();

        #pragma unroll
        for (int ks = 0; ks < 2; ks++) {
            int k0 = ks * 16;        // chunk-local
            int kg = k0g + k0;       // global k for Ws
            unsigned a0, a1, a2, a3;
            {
                unsigned addr = (unsigned)__cvta_generic_to_shared(
                    &As[m_base + (lane & 15)][k0 + ((lane >> 4) << 3)]);
                asm volatile("ldmatrix.sync.aligned.m8n8.x4.shared.b16 "
                             "{%0,%1,%2,%3}, [%4];"
                             : "=r"(a0), "=r"(a1), "=r"(a2), "=r"(a3) : "r"(addr));
            }
            #pragma unroll
            for (int nt = 0; nt < 8; nt++) {   // n16 tiles
                int n0 = nt * 16;
                unsigned b0, b1, b2, b3;
                unsigned addr = (unsigned)__cvta_generic_to_shared(
                    &Ws[kg + (lane & 15)][n0 + ((lane >> 4) << 3)]);
                asm volatile("ldmatrix.sync.aligned.m8n8.x4.trans.shared.b16 "
                             "{%0,%1,%2,%3}, [%4];"
                             : "=r"(b0), "=r"(b1), "=r"(b2), "=r"(b3) : "r"(addr));
                mma16816(acc[2 * nt],     a0, a1, a2, a3, b0, b1);
                mma16816(acc[2 * nt + 1], a0, a1, a2, a3, b2, b3);
            }
        }
    }

    // Epilogue: fp16 half2 stores into g_h
    int gq = lane >> 2, tg = lane & 3;
    int r0 = rowBase + m_base + gq;
    int r1 = r0 + 8;
    #pragma unroll
    for (int t8 = 0; t8 < 16; t8++) {
        int n0 = t8 * 8 + 2 * tg;
        if (r0 < NN) *(__half2*)&g_h[(size_t)r0 * DIM + n0] =
            __floats2half2_rn(acc[t8][0], acc[t8][1]);
        if (r1 < NN) *(__half2*)&g_h[(size_t)r1 * DIM + n0] =
            __floats2half2_rn(acc[t8][2], acc[t8][3]);
    }
}

// ---------------- aggregation: one warp per node ----------------
__device__ __forceinline__ void gather_fma(float4 &acc, float n, uint2 raw) {
    float2 f01 = __half22float2(*(__half2*)&raw.x);
    float2 f23 = __half22float2(*(__half2*)&raw.y);
    acc.x += n * f01.x; acc.y += n * f01.y;
    acc.z += n * f23.x; acc.w += n * f23.y;
}

template<bool TO_OUT>
__global__ __launch_bounds__(256) void k_agg(const float* __restrict__ bias,
                                             float* __restrict__ outp) {
    int warp = (blockIdx.x * blockDim.x + threadIdx.x) >> 5;
    int lane = threadIdx.x & 31;
    if (warp >= NN) return;
    int node = warp;

    float di = g_dinv[node];
    float sn = di * di;              // self-loop norm (weight 1)

    const uint2* hrow = (const uint2*)(g_h + (size_t)node * DIM);
    float4 acc = make_float4(0.f, 0.f, 0.f, 0.f);
    gather_fma(acc, sn, hrow[lane]);

    int start = g_off[node];
    int cnt   = g_cnt[node];

    int e = 0;
    for (; e + 2 <= cnt; e += 2) {
        int2 e0 = g_edge[start + e];
        int2 e1 = g_edge[start + e + 1];
        uint2 v0 = ((const uint2*)(g_h + (size_t)e0.x * DIM))[lane];
        uint2 v1 = ((const uint2*)(g_h + (size_t)e1.x * DIM))[lane];
        gather_fma(acc, __int_as_float(e0.y), v0);
        gather_fma(acc, __int_as_float(e1.y), v1);
    }
    if (e < cnt) {
        int2 e0 = g_edge[start + e];
        uint2 v0 = ((const uint2*)(g_h + (size_t)e0.x * DIM))[lane];
        gather_fma(acc, __int_as_float(e0.y), v0);
    }

    float4 bb = ((const float4*)bias)[lane];
    acc.x = fmaxf(acc.x + bb.x, 0.0f);
    acc.y = fmaxf(acc.y + bb.y, 0.0f);
    acc.z = fmaxf(acc.z + bb.z, 0.0f);
    acc.w = fmaxf(acc.w + bb.w, 0.0f);

    float4* dst = TO_OUT ? (float4*)outp : (float4*)g_z;
    dst[(size_t)node * 32 + lane] = acc;
}

// ---------------- launch: kernel launches ONLY ----------------
extern "C" void kernel_launch(void* const* d_in, const int* in_sizes, int n_in,
                              void* d_out, int out_size) {
    const float* x  = (const float*)d_in[0];
    const void*  ei = d_in[1];                    // int32 or int64 -> detected on device
    const float* ew = (const float*)d_in[2];
    const float* W1 = (const float*)d_in[3];
    const float* b1 = (const float*)d_in[4];
    const float* W2 = (const float*)d_in[5];
    const float* b2 = (const float*)d_in[6];
    float* out = (float*)d_out;

    const int gemm_grid = (NN + GEMM_BM - 1) / GEMM_BM;   // 782
    const int agg_grid  = (NN + 7) / 8;                    // 12500 (8 warps/block)

    // --- build + layer-1 GEMM (gemm1 independent of CSC build) ---
    k_init<<<(NN + 255) / 256, 256>>>((const int*)ei);
    k_hist<<<(NE + 255) / 256, 256>>>(ei, ew);
    k_scan1<<<SCAN_NBLK, SCAN_B>>>();
    k_scan2<<<1, 256>>>();
    k_scan3<<<SCAN_NBLK, SCAN_B>>>();
    k_gemm<false><<<gemm_grid, 256>>>(x, W1);     // x @ W1 -> g_h (fp16)
    k_scatter<<<(NE + 255) / 256, 256>>>(ei, ew);

    // --- layer 1 aggregate ---
    k_agg<false><<<agg_grid, 256>>>(b1, nullptr); // -> g_z (fp32)

    // --- layer 2 ---
    k_gemm<true><<<gemm_grid, 256>>>(nullptr, W2);
    k_agg<true><<<agg_grid, 256>>>(b2, out);
}

// round 10
// speedup vs baseline: 1.6410x; 1.1118x over previous
#include <cuda_runtime.h>
#include <cuda_fp16.h>

#define NN 100000
#define NE 1600000
#define DIM 128

#define SCAN_B 512
#define SCAN_NBLK ((NN + SCAN_B - 1) / SCAN_B)   // 196

typedef unsigned long long u64;

// ---------------- scratch (static device memory; no allocs) ----------------
__device__ __align__(16) float  g_deg[NN];     // 1 + sum(ew-1) during hist
__device__ __align__(16) float  g_dinv[NN];
__device__ __align__(16) int    g_cnt[NN];
__device__ __align__(16) int    g_off[NN];
__device__ __align__(16) int    g_cursor[NN];
__device__ __align__(16) int2   g_edge[NE];               // (src row, norm as int bits)
__device__ __align__(16) __half g_h[(size_t)NN * DIM];    // pre-agg features (A @ W), fp16
__device__ __align__(16) __half g_z16[(size_t)NN * DIM];  // layer-1 output, fp16
__device__ __align__(16) int    g_bsum[SCAN_NBLK];
__device__ int g_is64;                                    // edge_index dtype flag

// ---------------- init (+ edge dtype detect) ----------------
__global__ void k_init(const int* __restrict__ ei32) {
    int i = blockIdx.x * blockDim.x + threadIdx.x;
    if (i < NN) { g_deg[i] = 1.0f; g_cnt[i] = 0; }   // self-loop weight 1
    if (blockIdx.x == 0 && threadIdx.x == 0) {
        int is64 = 1;
        for (int j = 0; j < 64; j++)
            if (ei32[2 * j + 1] != 0) { is64 = 0; break; }
        g_is64 = is64;
    }
}

__device__ __forceinline__ int edge_at(const void* ei, int is64, size_t pos) {
    return is64 ? (int)((const long long*)ei)[pos] : ((const int*)ei)[pos];
}

// ---------------- degree / histogram ----------------
// deg = 1 + sum(ew). Int atomic counts edges; float atomic fires only for
// ew != 1 (never for unit weights). scan1 reconstructs deg = g_deg + cnt.
__global__ void k_hist(const void* __restrict__ ei, const float* __restrict__ ew) {
    int e = blockIdx.x * blockDim.x + threadIdx.x;
    if (e < NE) {
        int is64 = g_is64;
        int c = edge_at(ei, is64, (size_t)NE + e);   // col (destination)
        if ((unsigned)c < NN) {
            atomicAdd(&g_cnt[c], 1);
            float w = ew[e];
            if (w != 1.0f) atomicAdd(&g_deg[c], w - 1.0f);
        }
    }
}

// ---------------- scan phase 1 (+ dinv fused) ----------------
__global__ void k_scan1() {
    __shared__ int s[SCAN_B];
    int i = blockIdx.x * SCAN_B + threadIdx.x;
    int cnt = (i < NN) ? g_cnt[i] : 0;
    s[threadIdx.x] = cnt;
    if (i < NN) {
        float d = g_deg[i] + (float)cnt;
        g_dinv[i] = (d > 0.0f) ? rsqrtf(d) : 0.0f;
    }
    __syncthreads();
    for (int st = SCAN_B / 2; st > 0; st >>= 1) {
        if ((int)threadIdx.x < st) s[threadIdx.x] += s[threadIdx.x + st];
        __syncthreads();
    }
    if (threadIdx.x == 0) g_bsum[blockIdx.x] = s[0];
}

// ---------------- scan phase 2: per-block base computed in-block ----------
__global__ void k_scan3() {
    __shared__ int s[SCAN_B];
    __shared__ int sb[256];
    __shared__ int s_base;

    // base = sum of g_bsum[0 .. blockIdx.x-1], reduced by first 256 threads
    int t = threadIdx.x;
    if (t < 256) {
        sb[t] = (t < (int)blockIdx.x && t < SCAN_NBLK) ? g_bsum[t] : 0;
    }
    int i = blockIdx.x * SCAN_B + t;
    int v = (i < NN) ? g_cnt[i] : 0;
    s[t] = v;
    __syncthreads();
    if (t < 128) sb[t] += sb[t + 128];
    __syncthreads();
    if (t < 64) sb[t] += sb[t + 64];
    __syncthreads();
    if (t < 32) {
        int x = sb[t] + sb[t + 32];
        #pragma unroll
        for (int o = 16; o > 0; o >>= 1) x += __shfl_down_sync(0xffffffff, x, o);
        if (t == 0) s_base = x;
    }
    // Hillis-Steele inclusive scan of this block's counts
    for (int st = 1; st < SCAN_B; st <<= 1) {
        int u = 0;
        if (t >= st) u = s[t - st];
        __syncthreads();
        if (t >= st) s[t] += u;
        __syncthreads();
    }
    if (i < NN) {
        int excl = s_base + s[t] - v;
        g_off[i]    = excl;
        g_cursor[i] = excl;
    }
}

// ---------------- bucket edges by destination (CSC build) ----------------
__global__ void k_scatter(const void* __restrict__ ei, const float* __restrict__ ew) {
    int e = blockIdx.x * blockDim.x + threadIdx.x;
    if (e < NE) {
        int is64 = g_is64;
        int r = edge_at(ei, is64, e);
        int c = edge_at(ei, is64, (size_t)NE + e);
        if ((unsigned)r < NN && (unsigned)c < NN) {
            int pos = atomicAdd(&g_cursor[c], 1);
            float nrm = g_dinv[r] * ew[e] * g_dinv[c];
            g_edge[pos] = make_int2(r, __float_as_int(nrm));
        }
    }
}

// ---------------- tensor-core GEMM: g_h(fp16) = A[NN,128] @ W[128,128] -----
// mma.sync m16n8k16 f16/f32. 256 threads = 8 warps, warp owns m16 x n128.
// FROM_GZ=false: A = x (fp32 param). FROM_GZ=true: A = g_z16 (fp16 symbol).
#define GEMM_BM 128

__device__ __forceinline__ void mma16816(float* c, unsigned a0, unsigned a1,
                                         unsigned a2, unsigned a3,
                                         unsigned b0, unsigned b1) {
    asm volatile(
        "mma.sync.aligned.m16n8k16.row.col.f32.f16.f16.f32 "
        "{%0,%1,%2,%3}, {%4,%5,%6,%7}, {%8,%9}, {%0,%1,%2,%3};"
        : "+f"(c[0]), "+f"(c[1]), "+f"(c[2]), "+f"(c[3])
        : "r"(a0), "r"(a1), "r"(a2), "r"(a3), "r"(b0), "r"(b1));
}

template<bool FROM_GZ>
__global__ __launch_bounds__(256) void k_gemm(const float* __restrict__ Ain,
                                              const float* __restrict__ W) {
    __shared__ __half Ws[128][136];   // full W, k-major rows, padded
    __shared__ __half As[128][40];    // one k=32 chunk of A, padded (80B rows, 16B-aligned)

    int tid  = threadIdx.x;
    int wid  = tid >> 5;
    int lane = tid & 31;
    int rowBase = blockIdx.x * GEMM_BM;
    int m_base  = wid * 16;

    // Load + convert W (4096 float4 = 16384 floats)
    for (int i = tid; i < 4096; i += 256) {
        int r = i >> 5;              // 32 float4 per 128-col row
        int c = (i & 31) * 4;
        float4 w4 = *(const float4*)&W[r * DIM + c];
        *(__half2*)&Ws[r][c]     = __floats2half2_rn(w4.x, w4.y);
        *(__half2*)&Ws[r][c + 2] = __floats2half2_rn(w4.z, w4.w);
    }

    float acc[16][4];
    #pragma unroll
    for (int i = 0; i < 16; i++)
        #pragma unroll
        for (int j = 0; j < 4; j++) acc[i][j] = 0.0f;

    for (int kc = 0; kc < 4; kc++) {
        int k0g = kc * 32;
        __syncthreads();             // As reuse fence (covers Ws on iter 0)
        if (FROM_GZ) {
            // fp16 source: 128 rows x 32 halfs = 512 uint4
            for (int i = tid; i < 512; i += 256) {
                int r = i >> 2;              // 4 uint4 per row
                int c = (i & 3) * 8;
                int grow = rowBase + r;
                uint4 v = make_uint4(0u, 0u, 0u, 0u);
                if (grow < NN) v = *(const uint4*)&g_z16[(size_t)grow * DIM + k0g + c];
                *(uint4*)&As[r][c] = v;
            }
        } else {
            // fp32 source: 128 rows x 32 floats = 1024 float4, convert
            for (int i = tid; i < 1024; i += 256) {
                int r = i >> 3;
                int c = (i & 7) * 4;
                int grow = rowBase + r;
                float4 a4 = (grow < NN)
                    ? *(const float4*)&Ain[(size_t)grow * DIM + k0g + c]
                    : make_float4(0.f, 0.f, 0.f, 0.f);
                *(__half2*)&As[r][c]     = __floats2half2_rn(a4.x, a4.y);
                *(__half2*)&As[r][c + 2] = __floats2half2_rn(a4.z, a4.w);
            }
        }
        __syncthreads();

        #pragma unroll
        for (int ks = 0; ks < 2; ks++) {
            int k0 = ks * 16;
            int kg = k0g + k0;
            unsigned a0, a1, a2, a3;
            {
                unsigned addr = (unsigned)__cvta_generic_to_shared(
                    &As[m_base + (lane & 15)][k0 + ((lane >> 4) << 3)]);
                asm volatile("ldmatrix.sync.aligned.m8n8.x4.shared.b16 "
                             "{%0,%1,%2,%3}, [%4];"
                             : "=r"(a0), "=r"(a1), "=r"(a2), "=r"(a3) : "r"(addr));
            }
            #pragma unroll
            for (int nt = 0; nt < 8; nt++) {
                int n0 = nt * 16;
                unsigned b0, b1, b2, b3;
                unsigned addr = (unsigned)__cvta_generic_to_shared(
                    &Ws[kg + (lane & 15)][n0 + ((lane >> 4) << 3)]);
                asm volatile("ldmatrix.sync.aligned.m8n8.x4.trans.shared.b16 "
                             "{%0,%1,%2,%3}, [%4];"
                             : "=r"(b0), "=r"(b1), "=r"(b2), "=r"(b3) : "r"(addr));
                mma16816(acc[2 * nt],     a0, a1, a2, a3, b0, b1);
                mma16816(acc[2 * nt + 1], a0, a1, a2, a3, b2, b3);
            }
        }
    }

    // Epilogue: fp16 half2 stores into g_h
    int gq = lane >> 2, tg = lane & 3;
    int r0 = rowBase + m_base + gq;
    int r1 = r0 + 8;
    #pragma unroll
    for (int t8 = 0; t8 < 16; t8++) {
        int n0 = t8 * 8 + 2 * tg;
        if (r0 < NN) *(__half2*)&g_h[(size_t)r0 * DIM + n0] =
            __floats2half2_rn(acc[t8][0], acc[t8][1]);
        if (r1 < NN) *(__half2*)&g_h[(size_t)r1 * DIM + n0] =
            __floats2half2_rn(acc[t8][2], acc[t8][3]);
    }
}

// ---------------- aggregation: one warp per node, unroll-4 ----------------
__device__ __forceinline__ void gather_fma(float4 &acc, float n, uint2 raw) {
    float2 f01 = __half22float2(*(__half2*)&raw.x);
    float2 f23 = __half22float2(*(__half2*)&raw.y);
    acc.x += n * f01.x; acc.y += n * f01.y;
    acc.z += n * f23.x; acc.w += n * f23.y;
}

template<bool TO_OUT>
__global__ __launch_bounds__(128) void k_agg(const float* __restrict__ bias,
                                             float* __restrict__ outp) {
    int warp = (blockIdx.x * blockDim.x + threadIdx.x) >> 5;
    int lane = threadIdx.x & 31;
    if (warp >= NN) return;
    int node = warp;

    float di = g_dinv[node];
    float sn = di * di;              // self-loop norm (weight 1)

    const uint2* hrow = (const uint2*)(g_h + (size_t)node * DIM);
    float4 acc = make_float4(0.f, 0.f, 0.f, 0.f);
    gather_fma(acc, sn, hrow[lane]);

    int start = g_off[node];
    int cnt   = g_cnt[node];

    int e = 0;
    for (; e + 4 <= cnt; e += 4) {
        int2 E0 = g_edge[start + e];
        int2 E1 = g_edge[start + e + 1];
        int2 E2 = g_edge[start + e + 2];
        int2 E3 = g_edge[start + e + 3];
        uint2 V0 = ((const uint2*)(g_h + (size_t)E0.x * DIM))[lane];
        uint2 V1 = ((const uint2*)(g_h + (size_t)E1.x * DIM))[lane];
        uint2 V2 = ((const uint2*)(g_h + (size_t)E2.x * DIM))[lane];
        uint2 V3 = ((const uint2*)(g_h + (size_t)E3.x * DIM))[lane];
        gather_fma(acc, __int_as_float(E0.y), V0);
        gather_fma(acc, __int_as_float(E1.y), V1);
        gather_fma(acc, __int_as_float(E2.y), V2);
        gather_fma(acc, __int_as_float(E3.y), V3);
    }
    for (; e < cnt; e++) {
        int2 E0 = g_edge[start + e];
        uint2 V0 = ((const uint2*)(g_h + (size_t)E0.x * DIM))[lane];
        gather_fma(acc, __int_as_float(E0.y), V0);
    }

    float4 bb = ((const float4*)bias)[lane];
    acc.x = fmaxf(acc.x + bb.x, 0.0f);
    acc.y = fmaxf(acc.y + bb.y, 0.0f);
    acc.z = fmaxf(acc.z + bb.z, 0.0f);
    acc.w = fmaxf(acc.w + bb.w, 0.0f);

    if (TO_OUT) {
        ((float4*)outp)[(size_t)node * 32 + lane] = acc;
    } else {
        // fp16 store — numerically identical to fp32 store + fp16 load in gemm2
        __half2 p0 = __floats2half2_rn(acc.x, acc.y);
        __half2 p1 = __floats2half2_rn(acc.z, acc.w);
        uint2 v;
        v.x = *(unsigned*)&p0; v.y = *(unsigned*)&p1;
        *(uint2*)&g_z16[(size_t)node * DIM + lane * 4] = v;
    }
}

// ---------------- launch: kernel launches ONLY ----------------
extern "C" void kernel_launch(void* const* d_in, const int* in_sizes, int n_in,
                              void* d_out, int out_size) {
    const float* x  = (const float*)d_in[0];
    const void*  ei = d_in[1];                    // int32 or int64 -> detected on device
    const float* ew = (const float*)d_in[2];
    const float* W1 = (const float*)d_in[3];
    const float* b1 = (const float*)d_in[4];
    const float* W2 = (const float*)d_in[5];
    const float* b2 = (const float*)d_in[6];
    float* out = (float*)d_out;

    const int gemm_grid = (NN + GEMM_BM - 1) / GEMM_BM;   // 782
    const int agg_grid  = (NN * 32 + 127) / 128;          // 4 warps/block -> 25000

    // --- layer-1 GEMM first (independent of CSC build), then build ---
    k_gemm<false><<<gemm_grid, 256>>>(x, W1);     // x @ W1 -> g_h (fp16)
    k_init<<<(NN + 255) / 256, 256>>>((const int*)ei);
    k_hist<<<(NE + 255) / 256, 256>>>(ei, ew);
    k_scan1<<<SCAN_NBLK, SCAN_B>>>();
    k_scan3<<<SCAN_NBLK, SCAN_B>>>();
    k_scatter<<<(NE + 255) / 256, 256>>>(ei, ew);

    // --- layer 1 aggregate -> g_z16 (fp16) ---
    k_agg<false><<<agg_grid, 128>>>(b1, nullptr);

    // --- layer 2 ---
    k_gemm<true><<<gemm_grid, 256>>>(nullptr, W2);
    k_agg<true><<<agg_grid, 128>>>(b2, out);
}

// round 13
// speedup vs baseline: 1.7535x; 1.0686x over previous
#include <cuda_runtime.h>
#include <cuda_fp16.h>

#define NN 100000
#define NE 1600000
#define DIM 128

#define SCAN_B 512
#define SCAN_NBLK ((NN + SCAN_B - 1) / SCAN_B)   // 196

typedef unsigned long long u64;

// ---------------- scratch (static device memory; no allocs) ----------------
__device__ __align__(16) float  g_deg[NN];     // 1 + sum(ew-1) during hist
__device__ __align__(16) float  g_dinv[NN];
__device__ __align__(16) int    g_cnt[NN];
__device__ __align__(16) int    g_off[NN];
__device__ __align__(16) int    g_cursor[NN];
__device__ __align__(16) int2   g_edge[NE];               // (src row, norm as int bits)
__device__ __align__(16) __half g_h[(size_t)NN * DIM];    // pre-agg features (A @ W), fp16
__device__ __align__(16) __half g_z16[(size_t)NN * DIM];  // layer-1 output, fp16
__device__ __align__(16) int    g_bsum[SCAN_NBLK];
__device__ int g_is64;                                    // edge_index dtype flag

// ---------------- init (+ edge dtype detect) ----------------
__global__ void k_init(const int* __restrict__ ei32) {
    int i = blockIdx.x * blockDim.x + threadIdx.x;
    if (i < NN) { g_deg[i] = 1.0f; g_cnt[i] = 0; }   // self-loop weight 1
    if (blockIdx.x == 0 && threadIdx.x == 0) {
        int is64 = 1;
        for (int j = 0; j < 64; j++)
            if (ei32[2 * j + 1] != 0) { is64 = 0; break; }
        g_is64 = is64;
    }
}

__device__ __forceinline__ int edge_at(const void* ei, int is64, size_t pos) {
    return is64 ? (int)((const long long*)ei)[pos] : ((const int*)ei)[pos];
}

// ---------------- degree / histogram ----------------
// deg = 1 + sum(ew). Int atomic counts edges; float atomic fires only for
// ew != 1 (never for unit weights). scan1 reconstructs deg = g_deg + cnt.
__global__ void k_hist(const void* __restrict__ ei, const float* __restrict__ ew) {
    int e = blockIdx.x * blockDim.x + threadIdx.x;
    if (e < NE) {
        int is64 = g_is64;
        int c = edge_at(ei, is64, (size_t)NE + e);   // col (destination)
        if ((unsigned)c < NN) {
            atomicAdd(&g_cnt[c], 1);
            float w = ew[e];
            if (w != 1.0f) atomicAdd(&g_deg[c], w - 1.0f);
        }
    }
}

// ---------------- scan phase 1 (+ dinv fused) ----------------
__global__ void k_scan1() {
    __shared__ int s[SCAN_B];
    int i = blockIdx.x * SCAN_B + threadIdx.x;
    int cnt = (i < NN) ? g_cnt[i] : 0;
    s[threadIdx.x] = cnt;
    if (i < NN) {
        float d = g_deg[i] + (float)cnt;
        g_dinv[i] = (d > 0.0f) ? rsqrtf(d) : 0.0f;
    }
    __syncthreads();
    for (int st = SCAN_B / 2; st > 0; st >>= 1) {
        if ((int)threadIdx.x < st) s[threadIdx.x] += s[threadIdx.x + st];
        __syncthreads();
    }
    if (threadIdx.x == 0) g_bsum[blockIdx.x] = s[0];
}

// ---------------- scan phase 2: per-block base computed in-block ----------
__global__ void k_scan3() {
    __shared__ int s[SCAN_B];
    __shared__ int sb[256];
    __shared__ int s_base;

    int t = threadIdx.x;
    if (t < 256) {
        sb[t] = (t < (int)blockIdx.x && t < SCAN_NBLK) ? g_bsum[t] : 0;
    }
    int i = blockIdx.x * SCAN_B + t;
    int v = (i < NN) ? g_cnt[i] : 0;
    s[t] = v;
    __syncthreads();
    if (t < 128) sb[t] += sb[t + 128];
    __syncthreads();
    if (t < 64) sb[t] += sb[t + 64];
    __syncthreads();
    if (t < 32) {
        int x = sb[t] + sb[t + 32];
        #pragma unroll
        for (int o = 16; o > 0; o >>= 1) x += __shfl_down_sync(0xffffffff, x, o);
        if (t == 0) s_base = x;
    }
    for (int st = 1; st < SCAN_B; st <<= 1) {
        int u = 0;
        if (t >= st) u = s[t - st];
        __syncthreads();
        if (t >= st) s[t] += u;
        __syncthreads();
    }
    if (i < NN) {
        int excl = s_base + s[t] - v;
        g_off[i]    = excl;
        g_cursor[i] = excl;
    }
}

// ---------------- bucket edges by destination (CSC build) ----------------
__global__ void k_scatter(const void* __restrict__ ei, const float* __restrict__ ew) {
    int e = blockIdx.x * blockDim.x + threadIdx.x;
    if (e < NE) {
        int is64 = g_is64;
        int r = edge_at(ei, is64, e);
        int c = edge_at(ei, is64, (size_t)NE + e);
        if ((unsigned)r < NN && (unsigned)c < NN) {
            int pos = atomicAdd(&g_cursor[c], 1);
            float nrm = g_dinv[r] * ew[e] * g_dinv[c];
            g_edge[pos] = make_int2(r, __float_as_int(nrm));
        }
    }
}

// ---------------- tensor-core GEMM: g_h(fp16) = A[NN,128] @ W[128,128] -----
// mma.sync m16n8k16 f16/f32. 256 threads = 8 warps, warp owns m16 x n128.
// FROM_GZ=false: A = x (fp32 param). FROM_GZ=true: A = g_z16 (fp16 symbol).
#define GEMM_BM 128

__device__ __forceinline__ void mma16816(float* c, unsigned a0, unsigned a1,
                                         unsigned a2, unsigned a3,
                                         unsigned b0, unsigned b1) {
    asm volatile(
        "mma.sync.aligned.m16n8k16.row.col.f32.f16.f16.f32 "
        "{%0,%1,%2,%3}, {%4,%5,%6,%7}, {%8,%9}, {%0,%1,%2,%3};"
        : "+f"(c[0]), "+f"(c[1]), "+f"(c[2]), "+f"(c[3])
        : "r"(a0), "r"(a1), "r"(a2), "r"(a3), "r"(b0), "r"(b1));
}

template<bool FROM_GZ>
__global__ __launch_bounds__(256) void k_gemm(const float* __restrict__ Ain,
                                              const float* __restrict__ W) {
    __shared__ __half Ws[128][136];   // full W, k-major rows, padded
    __shared__ __half As[128][40];    // one k=32 chunk of A, padded

    int tid  = threadIdx.x;
    int wid  = tid >> 5;
    int lane = tid & 31;
    int rowBase = blockIdx.x * GEMM_BM;
    int m_base  = wid * 16;

    // Load + convert W (4096 float4 = 16384 floats)
    for (int i = tid; i < 4096; i += 256) {
        int r = i >> 5;
        int c = (i & 31) * 4;
        float4 w4 = *(const float4*)&W[r * DIM + c];
        *(__half2*)&Ws[r][c]     = __floats2half2_rn(w4.x, w4.y);
        *(__half2*)&Ws[r][c + 2] = __floats2half2_rn(w4.z, w4.w);
    }

    float acc[16][4];
    #pragma unroll
    for (int i = 0; i < 16; i++)
        #pragma unroll
        for (int j = 0; j < 4; j++) acc[i][j] = 0.0f;

    for (int kc = 0; kc < 4; kc++) {
        int k0g = kc * 32;
        __syncthreads();             // As reuse fence (covers Ws on iter 0)
        if (FROM_GZ) {
            for (int i = tid; i < 512; i += 256) {
                int r = i >> 2;
                int c = (i & 3) * 8;
                int grow = rowBase + r;
                uint4 v = make_uint4(0u, 0u, 0u, 0u);
                if (grow < NN) v = *(const uint4*)&g_z16[(size_t)grow * DIM + k0g + c];
                *(uint4*)&As[r][c] = v;
            }
        } else {
            for (int i = tid; i < 1024; i += 256) {
                int r = i >> 3;
                int c = (i & 7) * 4;
                int grow = rowBase + r;
                float4 a4 = (grow < NN)
                    ? *(const float4*)&Ain[(size_t)grow * DIM + k0g + c]
                    : make_float4(0.f, 0.f, 0.f, 0.f);
                *(__half2*)&As[r][c]     = __floats2half2_rn(a4.x, a4.y);
                *(__half2*)&As[r][c + 2] = __floats2half2_rn(a4.z, a4.w);
            }
        }
        __syncthreads();

        #pragma unroll
        for (int ks = 0; ks < 2; ks++) {
            int k0 = ks * 16;
            int kg = k0g + k0;
            unsigned a0, a1, a2, a3;
            {
                unsigned addr = (unsigned)__cvta_generic_to_shared(
                    &As[m_base + (lane & 15)][k0 + ((lane >> 4) << 3)]);
                asm volatile("ldmatrix.sync.aligned.m8n8.x4.shared.b16 "
                             "{%0,%1,%2,%3}, [%4];"
                             : "=r"(a0), "=r"(a1), "=r"(a2), "=r"(a3) : "r"(addr));
            }
            #pragma unroll
            for (int nt = 0; nt < 8; nt++) {
                int n0 = nt * 16;
                unsigned b0, b1, b2, b3;
                unsigned addr = (unsigned)__cvta_generic_to_shared(
                    &Ws[kg + (lane & 15)][n0 + ((lane >> 4) << 3)]);
                asm volatile("ldmatrix.sync.aligned.m8n8.x4.trans.shared.b16 "
                             "{%0,%1,%2,%3}, [%4];"
                             : "=r"(b0), "=r"(b1), "=r"(b2), "=r"(b3) : "r"(addr));
                mma16816(acc[2 * nt],     a0, a1, a2, a3, b0, b1);
                mma16816(acc[2 * nt + 1], a0, a1, a2, a3, b2, b3);
            }
        }
    }

    // Epilogue: fp16 half2 stores into g_h
    int gq = lane >> 2, tg = lane & 3;
    int r0 = rowBase + m_base + gq;
    int r1 = r0 + 8;
    #pragma unroll
    for (int t8 = 0; t8 < 16; t8++) {
        int n0 = t8 * 8 + 2 * tg;
        if (r0 < NN) *(__half2*)&g_h[(size_t)r0 * DIM + n0] =
            __floats2half2_rn(acc[t8][0], acc[t8][1]);
        if (r1 < NN) *(__half2*)&g_h[(size_t)r1 * DIM + n0] =
            __floats2half2_rn(acc[t8][2], acc[t8][3]);
    }
}

// ---------------- aggregation: one warp per node, unroll-4 ----------------
__device__ __forceinline__ void gather_fma(float4 &acc, float n, uint2 raw) {
    float2 f01 = __half22float2(*(__half2*)&raw.x);
    float2 f23 = __half22float2(*(__half2*)&raw.y);
    acc.x += n * f01.x; acc.y += n * f01.y;
    acc.z += n * f23.x; acc.w += n * f23.y;
}

template<bool TO_OUT>
__global__ __launch_bounds__(128) void k_agg(const float* __restrict__ bias,
                                             float* __restrict__ outp) {
    int warp = (blockIdx.x * blockDim.x + threadIdx.x) >> 5;
    int lane = threadIdx.x & 31;
    if (warp >= NN) return;
    int node = warp;

    float di = g_dinv[node];
    float sn = di * di;              // self-loop norm (weight 1)

    const uint2* hrow = (const uint2*)(g_h + (size_t)node * DIM);
    float4 acc = make_float4(0.f, 0.f, 0.f, 0.f);
    gather_fma(acc, sn, hrow[lane]);

    int start = g_off[node];
    int cnt   = g_cnt[node];

    int e = 0;
    for (; e + 4 <= cnt; e += 4) {
        int2 E0 = g_edge[start + e];
        int2 E1 = g_edge[start + e + 1];
        int2 E2 = g_edge[start + e + 2];
        int2 E3 = g_edge[start + e + 3];
        uint2 V0 = ((const uint2*)(g_h + (size_t)E0.x * DIM))[lane];
        uint2 V1 = ((const uint2*)(g_h + (size_t)E1.x * DIM))[lane];
        uint2 V2 = ((const uint2*)(g_h + (size_t)E2.x * DIM))[lane];
        uint2 V3 = ((const uint2*)(g_h + (size_t)E3.x * DIM))[lane];
        gather_fma(acc, __int_as_float(E0.y), V0);
        gather_fma(acc, __int_as_float(E1.y), V1);
        gather_fma(acc, __int_as_float(E2.y), V2);
        gather_fma(acc, __int_as_float(E3.y), V3);
    }
    for (; e < cnt; e++) {
        int2 E0 = g_edge[start + e];
        uint2 V0 = ((const uint2*)(g_h + (size_t)E0.x * DIM))[lane];
        gather_fma(acc, __int_as_float(E0.y), V0);
    }

    float4 bb = ((const float4*)bias)[lane];
    acc.x = fmaxf(acc.x + bb.x, 0.0f);
    acc.y = fmaxf(acc.y + bb.y, 0.0f);
    acc.z = fmaxf(acc.z + bb.z, 0.0f);
    acc.w = fmaxf(acc.w + bb.w, 0.0f);

    if (TO_OUT) {
        ((float4*)outp)[(size_t)node * 32 + lane] = acc;
    } else {
        // fp16 store — numerically identical to fp32 store + fp16 load in gemm2
        __half2 p0 = __floats2half2_rn(acc.x, acc.y);
        __half2 p1 = __floats2half2_rn(acc.z, acc.w);
        uint2 v;
        v.x = *(unsigned*)&p0; v.y = *(unsigned*)&p1;
        *(uint2*)&g_z16[(size_t)node * DIM + lane * 4] = v;
    }
}

// ---------------- launch: fork-join overlap of build chain with GEMM1 ------
extern "C" void kernel_launch(void* const* d_in, const int* in_sizes, int n_in,
                              void* d_out, int out_size) {
    const float* x  = (const float*)d_in[0];
    const void*  ei = d_in[1];                    // int32 or int64 -> detected on device
    const float* ew = (const float*)d_in[2];
    const float* W1 = (const float*)d_in[3];
    const float* b1 = (const float*)d_in[4];
    const float* W2 = (const float*)d_in[5];
    const float* b2 = (const float*)d_in[6];
    float* out = (float*)d_out;

    const int gemm_grid = (NN + GEMM_BM - 1) / GEMM_BM;   // 782
    const int agg_grid  = (NN * 32 + 127) / 128;          // 25000

    // one-time host objects (no device memory)
    static cudaStream_t s2 = nullptr;
    static cudaEvent_t  eFork = nullptr, eJoin = nullptr;
    if (!s2) {
        cudaStreamCreateWithFlags(&s2, cudaStreamNonBlocking);
        cudaEventCreateWithFlags(&eFork, cudaEventDisableTiming);
        cudaEventCreateWithFlags(&eJoin, cudaEventDisableTiming);
    }

    // fork: side stream builds CSC while main stream runs GEMM1
    cudaEventRecord(eFork, 0);
    cudaStreamWaitEvent(s2, eFork, 0);

    k_gemm<false><<<gemm_grid, 256>>>(x, W1);            // main: x @ W1 -> g_h

    k_init<<<(NN + 255) / 256, 256, 0, s2>>>((const int*)ei);
    k_hist<<<(NE + 255) / 256, 256, 0, s2>>>(ei, ew);
    k_scan1<<<SCAN_NBLK, SCAN_B, 0, s2>>>();
    k_scan3<<<SCAN_NBLK, SCAN_B, 0, s2>>>();
    k_scatter<<<(NE + 255) / 256, 256, 0, s2>>>(ei, ew);

    // join
    cudaEventRecord(eJoin, s2);
    cudaStreamWaitEvent(0, eJoin, 0);

    // --- layer 1 aggregate -> g_z16 (fp16) ---
    k_agg<false><<<agg_grid, 128>>>(b1, nullptr);

    // --- layer 2 ---
    k_gemm<true><<<gemm_grid, 256>>>(nullptr, W2);
    k_agg<true><<<agg_grid, 128>>>(b2, out);
}